// round 2
// baseline (speedup 1.0000x reference)
#include <cuda_runtime.h>
#include <cstdint>

// Problem constants (fixed shapes: B=1, N=64, X=256, Y=256, Z=32)
#define NINST 64
#define V (256*256*32)                 // 2,097,152 voxels / instance
#define WORDS_PER_INST (V/32)          // 65536 uint32 words / instance
#define CHUNK_WORDS 128                // words per block per instance
#define CHUNK_VOX  (CHUNK_WORDS*32)    // 4096 voxels per block per instance
#define NBLOCKS (WORDS_PER_INST/CHUNK_WORDS)  // 512 blocks
#define NSLOT 64                       // partial accumulation slots

// Partial pairwise-intersection accumulators: NSLOT x 64 x 64 uint32 = 1 MB
__device__ unsigned int g_partial[NSLOT * NINST * NINST];

// ---------------------------------------------------------------------------
// Kernel 0: zero the partial accumulators (graph replays must start clean)
// ---------------------------------------------------------------------------
__global__ void zero_kernel() {
    const int total = NSLOT * NINST * NINST;
    for (int i = blockIdx.x * blockDim.x + threadIdx.x; i < total;
         i += gridDim.x * blockDim.x)
        g_partial[i] = 0u;
}

// ---------------------------------------------------------------------------
// Kernel 1 (fused): pack 0/1 float masks to bits (ballot) for a voxel chunk
// across ALL 64 instances, then compute the 64x64 partial intersection counts
// for that chunk via register-tiled AND+popcount out of shared memory.
// ---------------------------------------------------------------------------
__global__ __launch_bounds__(256) void pack_inter_kernel(
    const unsigned int* __restrict__ mask)  // float bits: 0x0 or 0x3f800000
{
    // sm[w][inst]: packed words, transposed so a 4x4 pair tile reads uint4s
    __shared__ unsigned int sm[CHUNK_WORDS][NINST];

    const int tid  = threadIdx.x;
    const int lane = tid & 31;
    const int wp   = tid >> 5;           // warp 0..7
    const int b    = blockIdx.x;

    // ---------------- Phase A: pack chunk for every instance ----------------
    // Warp wp covers voxels [wp*512, wp*512+512) of this block's chunk,
    // in 4 passes of 128 voxels (one float4 / lane / pass).
    const unsigned int* base =
        mask + (size_t)b * CHUNK_VOX + (size_t)wp * 512 + (size_t)lane * 4;
    const int w0 = wp * 16;  // first local word index for this warp

    for (int i = 0; i < NINST; i++) {
        const uint4* p = (const uint4*)(base + (size_t)i * V);
        // 4 independent 16B loads up front (MLP=4)
        uint4 v0 = p[0];    // voxels +0
        uint4 v1 = p[32];   // voxels +128
        uint4 v2 = p[64];   // voxels +256
        uint4 v3 = p[96];   // voxels +384

#define BAL(v, pp)                                                       \
        {                                                                \
            unsigned b0 = __ballot_sync(0xffffffffu, (v).x != 0u);       \
            unsigned b1 = __ballot_sync(0xffffffffu, (v).y != 0u);       \
            unsigned b2 = __ballot_sync(0xffffffffu, (v).z != 0u);       \
            unsigned b3 = __ballot_sync(0xffffffffu, (v).w != 0u);       \
            if (lane == 0) {                                             \
                sm[w0 + (pp)*4 + 0][i] = b0;                             \
                sm[w0 + (pp)*4 + 1][i] = b1;                             \
                sm[w0 + (pp)*4 + 2][i] = b2;                             \
                sm[w0 + (pp)*4 + 3][i] = b3;                             \
            }                                                            \
        }
        BAL(v0, 0) BAL(v1, 1) BAL(v2, 2) BAL(v3, 3)
#undef BAL
    }
    __syncthreads();

    // ------------- Phase B: 64x64 partial intersections from smem ----------
    // 4x4 pair tile per thread. Warp lane map (8 ti x 4 tj) is bank-conflict
    // free: i-loads hit 8 distinct 16B groups, j-loads hit 4 (broadcast).
    const int ti = ((wp & 1) << 3) + (lane & 7);   // 0..15
    const int tj = ((wp >> 1) << 2) + (lane >> 3); // 0..15
    const int i0 = ti * 4, j0 = tj * 4;

    unsigned acc[4][4];
#pragma unroll
    for (int r = 0; r < 4; r++)
#pragma unroll
        for (int c = 0; c < 4; c++) acc[r][c] = 0u;

    for (int w = 0; w < CHUNK_WORDS; w += 2) {
        uint4 A0 = *(const uint4*)&sm[w][i0];
        uint4 B0 = *(const uint4*)&sm[w][j0];
        uint4 A1 = *(const uint4*)&sm[w + 1][i0];
        uint4 B1 = *(const uint4*)&sm[w + 1][j0];
        unsigned a0[4] = {A0.x, A0.y, A0.z, A0.w};
        unsigned b0[4] = {B0.x, B0.y, B0.z, B0.w};
        unsigned a1[4] = {A1.x, A1.y, A1.z, A1.w};
        unsigned b1[4] = {B1.x, B1.y, B1.z, B1.w};
#pragma unroll
        for (int r = 0; r < 4; r++)
#pragma unroll
            for (int c = 0; c < 4; c++)
                acc[r][c] += __popc(a0[r] & b0[c]) + __popc(a1[r] & b1[c]);
    }

    // One atomic per matrix entry per block, spread over NSLOT slots.
    unsigned* gp = g_partial + (unsigned)(b & (NSLOT - 1)) * (NINST * NINST);
#pragma unroll
    for (int r = 0; r < 4; r++)
#pragma unroll
        for (int c = 0; c < 4; c++)
            atomicAdd(&gp[(i0 + r) * NINST + (j0 + c)], acc[r][c]);
}

// ---------------------------------------------------------------------------
// Kernel 2: reduce partial slots, then exact-integer sequential NMS,
// warp-vectorized over j with ballots. Writes float32 (0.0/1.0) output.
// ---------------------------------------------------------------------------
__global__ void nms_kernel(float* __restrict__ out) {
    __shared__ unsigned int inter[NINST * NINST];
    __shared__ unsigned int ssc[NINST];

    const int t = threadIdx.x;  // 256 threads
    for (int e = t; e < NINST * NINST; e += 256) {
        unsigned s = 0;
#pragma unroll
        for (int k = 0; k < NSLOT; k++) s += g_partial[k * NINST * NINST + e];
        inter[e] = s;
    }
    __syncthreads();
    if (t < NINST) ssc[t] = inter[t * NINST + t];  // score = diag(inter)
    __syncthreads();

    if (t < 32) {
        const int lane = t;
        const unsigned sj0 = ssc[lane];
        const unsigned sj1 = ssc[lane + 32];
        unsigned long long ind = ~0ULL;  // all 64 instances kept

        for (int i = 0; i < NINST; i++) {
            if (!((ind >> i) & 1ULL)) continue;  // uniform across warp
            const unsigned si  = ssc[i];
            const unsigned in0 = inter[i * NINST + lane];
            const unsigned in1 = inter[i * NINST + lane + 32];
            // iou > 0.5  <=>  2*inter > union  (exact: counts < 2^23)
            // union == 0 => inter == 0 => false, matching NaN > 0.5 == false
            const bool h0 = (2u * in0 > si + sj0 - in0);
            const bool h1 = (2u * in1 > si + sj1 - in1);
            unsigned a0 = __ballot_sync(0xffffffffu, h0 && (si > sj0));
            unsigned a1 = __ballot_sync(0xffffffffu, h1 && (si > sj1));
            unsigned c0 = __ballot_sync(0xffffffffu, h0 && (sj0 > si));
            unsigned c1 = __ballot_sync(0xffffffffu, h1 && (sj1 > si));
            unsigned long long A  = ((unsigned long long)a1 << 32) | a0;
            unsigned long long Bm = ((unsigned long long)c1 << 32) | c0;
            if (A) {
                // first j where (hit && s_i > s_j): suppress j, break
                int jb = __ffsll((long long)A) - 1;
                unsigned long long before = (1ULL << jb) - 1ULL;
                if (Bm & before) ind &= ~(1ULL << i);  // some earlier j beat i
                ind &= ~(1ULL << jb);
            } else {
                if (Bm) ind &= ~(1ULL << i);  // no break: all j checked
            }
        }
        out[lane]      = (float)((ind >> lane) & 1ULL);
        out[lane + 32] = (float)((ind >> (lane + 32)) & 1ULL);
    }
}

// ---------------------------------------------------------------------------
extern "C" void kernel_launch(void* const* d_in, const int* in_sizes, int n_in,
                              void* d_out, int out_size) {
    const unsigned int* mask = (const unsigned int*)d_in[0];
    zero_kernel<<<256, 256>>>();
    pack_inter_kernel<<<NBLOCKS, 256>>>(mask);
    nms_kernel<<<1, 256>>>((float*)d_out);
}

// round 3
// speedup vs baseline: 1.3389x; 1.3389x over previous
#include <cuda_runtime.h>
#include <cstdint>

// Fixed shapes: B=1, N=64, X=256, Y=256, Z=32
#define NINST 64
#define V (256*256*32)                      // 2,097,152 voxels / instance
#define WORDS_PER_INST (V/32)               // 65536 packed words / instance
#define CHUNK_WORDS 16                      // words per chunk
#define CHUNK_VOX (CHUNK_WORDS*32)          // 512 voxels per chunk
#define NCHUNK (WORDS_PER_INST/CHUNK_WORDS) // 4096 chunks
#define DSTAGE 16                           // TMA pipeline depth (divides NINST)
#define TMA_BYTES (CHUNK_VOX*4)             // 2048 bytes per bulk load
#define NBLK 888                            // 148 SMs * 6 blocks
#define NSLOT 16                            // partial accumulator slots

// Partial pairwise-intersection accumulators (zero-initialized at load;
// nms_kernel re-zeroes them after consuming, so every replay starts clean).
__device__ unsigned int g_partial[NSLOT * NINST * NINST];
__device__ unsigned int g_ticket;   // dynamic chunk ticket, reset by nms_kernel

// ---------------------------------------------------------------------------
// PTX helpers (sm_90+ bulk-async + mbarrier)
// ---------------------------------------------------------------------------
__device__ __forceinline__ unsigned su32(const void* p) {
    return (unsigned)__cvta_generic_to_shared(p);
}
__device__ __forceinline__ void mbar_init(unsigned a, unsigned cnt) {
    asm volatile("mbarrier.init.shared.b64 [%0], %1;" :: "r"(a), "r"(cnt) : "memory");
}
__device__ __forceinline__ void mbar_expect_tx(unsigned a, unsigned tx) {
    asm volatile("mbarrier.arrive.expect_tx.shared.b64 _, [%0], %1;"
                 :: "r"(a), "r"(tx) : "memory");
}
__device__ __forceinline__ void mbar_wait(unsigned a, unsigned parity) {
    asm volatile(
        "{\n\t.reg .pred p;\n\t"
        "WAIT_%=:\n\t"
        "mbarrier.try_wait.parity.acquire.cta.shared::cta.b64 p, [%0], %1, 0x989680;\n\t"
        "@!p bra WAIT_%=;\n\t}"
        :: "r"(a), "r"(parity) : "memory");
}
__device__ __forceinline__ void tma_bulk(unsigned dst, const void* src,
                                         unsigned bytes, unsigned mbar) {
    asm volatile(
        "cp.async.bulk.shared::cta.global.mbarrier::complete_tx::bytes [%0], [%1], %2, [%3];"
        :: "r"(dst), "l"(src), "r"(bytes), "r"(mbar) : "memory");
}

// ---------------------------------------------------------------------------
// Kernel 1: persistent fused pack + pairwise-popcount, TMA-fed.
// Each block grabs chunks (512 voxels x 64 instances = 128KB) via a global
// ticket, bulk-loads one instance-slice per pipeline stage, ballot-packs it
// to bits, and accumulates the 64x64 intersection counts in registers.
// ---------------------------------------------------------------------------
__global__ __launch_bounds__(256, 6) void pack_inter_kernel(
    const float* __restrict__ mask)
{
    __shared__ __align__(128) float raw[DSTAGE][CHUNK_VOX];        // 32 KB
    __shared__ __align__(128) unsigned packed[CHUNK_WORDS][NINST]; //  4 KB
    __shared__ __align__(8)   unsigned long long mbar[DSTAGE];
    __shared__ int s_chunk;

    const int tid  = threadIdx.x;
    const int lane = tid & 31;
    const int wp   = tid >> 5;

    if (tid == 0) {
        for (int s = 0; s < DSTAGE; s++) mbar_init(su32(&mbar[s]), 1);
        asm volatile("fence.proxy.async.shared::cta;" ::: "memory");
    }
    __syncthreads();

    // 16x16 pair-tile map (4x4 instances per thread), bank-conflict free.
    const int ti = ((wp & 1) << 3) + (lane & 7);
    const int tj = ((wp >> 1) << 2) + (lane >> 3);
    const int i0 = ti * 4, j0 = tj * 4;

    unsigned acc[4][4];
#pragma unroll
    for (int r = 0; r < 4; r++)
#pragma unroll
        for (int c2 = 0; c2 < 4; c2++) acc[r][c2] = 0u;

    const unsigned raw_rd = su32(&raw[0][0]) + (unsigned)(wp * 64 + lane * 2) * 4u;

    for (;;) {
        if (tid == 0) s_chunk = (int)atomicAdd(&g_ticket, 1u);
        __syncthreads();
        const int c = s_chunk;
        if (c >= NCHUNK) break;

        const float* src = mask + (size_t)c * CHUNK_VOX;

        // Prologue: fill all DSTAGE stages (instances 0..15).
        if (tid == 0) {
#pragma unroll
            for (int j = 0; j < DSTAGE; j++) {
                mbar_expect_tx(su32(&mbar[j]), TMA_BYTES);
                tma_bulk(su32(&raw[j][0]), src + (size_t)j * V, TMA_BYTES,
                         su32(&mbar[j]));
            }
        }

        // Steady state: consume instance j, refill stage with instance j+16.
        for (int j = 0; j < NINST; j++) {
            const int s = j & (DSTAGE - 1);
            mbar_wait(su32(&mbar[s]), (unsigned)((j >> 4) & 1));

            // Each warp packs 64 voxels -> 2 words (fixed permutation;
            // consistent across instances, so popcounts are unaffected).
            uint2 v;
            asm volatile("ld.shared.v2.u32 {%0,%1}, [%2];"
                         : "=r"(v.x), "=r"(v.y)
                         : "r"(raw_rd + (unsigned)s * (CHUNK_VOX * 4)));
            unsigned b0 = __ballot_sync(0xffffffffu, v.x != 0u);
            unsigned b1 = __ballot_sync(0xffffffffu, v.y != 0u);
            if (lane == 0) {
                packed[wp * 2][j]     = b0;
                packed[wp * 2 + 1][j] = b1;
            }
            __syncthreads();   // stage s fully consumed; packed[.][j] visible

            if (tid == 0 && j + DSTAGE < NINST) {
                const int jj = j + DSTAGE, ss = jj & (DSTAGE - 1);
                mbar_expect_tx(su32(&mbar[ss]), TMA_BYTES);
                tma_bulk(su32(&raw[ss][0]), src + (size_t)jj * V, TMA_BYTES,
                         su32(&mbar[ss]));
            }
        }

        // Phase B: accumulate this chunk's 64x64 intersections (registers).
#pragma unroll
        for (int w = 0; w < CHUNK_WORDS; w += 2) {
            uint4 A0 = *(const uint4*)&packed[w][i0];
            uint4 B0 = *(const uint4*)&packed[w][j0];
            uint4 A1 = *(const uint4*)&packed[w + 1][i0];
            uint4 B1 = *(const uint4*)&packed[w + 1][j0];
            unsigned a0[4] = {A0.x, A0.y, A0.z, A0.w};
            unsigned b0[4] = {B0.x, B0.y, B0.z, B0.w};
            unsigned a1[4] = {A1.x, A1.y, A1.z, A1.w};
            unsigned b1[4] = {B1.x, B1.y, B1.z, B1.w};
#pragma unroll
            for (int r = 0; r < 4; r++)
#pragma unroll
                for (int c2 = 0; c2 < 4; c2++)
                    acc[r][c2] += __popc(a0[r] & b0[c2]) + __popc(a1[r] & b1[c2]);
        }
        // ticket __syncthreads at loop head orders phase-B reads vs next packs
    }

    // Flush per-block totals once (16 atomics / thread, NSLOT-way spread).
    unsigned* gp = g_partial + (unsigned)(blockIdx.x & (NSLOT - 1)) * (NINST * NINST);
#pragma unroll
    for (int r = 0; r < 4; r++)
#pragma unroll
        for (int c2 = 0; c2 < 4; c2++)
            atomicAdd(&gp[(i0 + r) * NINST + (j0 + c2)], acc[r][c2]);
}

// ---------------------------------------------------------------------------
// Kernel 2: reduce slots, re-zero state for the next replay, exact-integer
// sequential NMS (warp-vectorized over j), float32 0/1 output.
// ---------------------------------------------------------------------------
__global__ void nms_kernel(float* __restrict__ out) {
    __shared__ unsigned int inter[NINST * NINST];
    __shared__ unsigned int ssc[NINST];

    const int t = threadIdx.x;  // 256 threads
    for (int e = t; e < NINST * NINST; e += 256) {
        unsigned s = 0;
#pragma unroll
        for (int k = 0; k < NSLOT; k++) s += g_partial[k * NINST * NINST + e];
        inter[e] = s;
    }
    __syncthreads();

    // Reset device state for the next graph replay.
    {
        uint4 z = make_uint4(0u, 0u, 0u, 0u);
        uint4* gp4 = (uint4*)g_partial;
        for (int e = t; e < (NSLOT * NINST * NINST) / 4; e += 256) gp4[e] = z;
        if (t == 0) g_ticket = 0u;
    }

    if (t < NINST) ssc[t] = inter[t * NINST + t];  // score = diag(inter)
    __syncthreads();

    if (t < 32) {
        const int lane = t;
        const unsigned sj0 = ssc[lane];
        const unsigned sj1 = ssc[lane + 32];
        unsigned long long ind = ~0ULL;

        for (int i = 0; i < NINST; i++) {
            if (!((ind >> i) & 1ULL)) continue;  // uniform across warp
            const unsigned si  = ssc[i];
            const unsigned in0 = inter[i * NINST + lane];
            const unsigned in1 = inter[i * NINST + lane + 32];
            // iou > 0.5  <=>  2*inter > union  (exact in integers; counts < 2^23)
            const bool h0 = (2u * in0 > si + sj0 - in0);
            const bool h1 = (2u * in1 > si + sj1 - in1);
            unsigned a0 = __ballot_sync(0xffffffffu, h0 && (si > sj0));
            unsigned a1 = __ballot_sync(0xffffffffu, h1 && (si > sj1));
            unsigned c0 = __ballot_sync(0xffffffffu, h0 && (sj0 > si));
            unsigned c1 = __ballot_sync(0xffffffffu, h1 && (sj1 > si));
            unsigned long long A  = ((unsigned long long)a1 << 32) | a0;
            unsigned long long Bm = ((unsigned long long)c1 << 32) | c0;
            if (A) {
                int jb = __ffsll((long long)A) - 1;   // first suppressed j (break)
                unsigned long long before = (1ULL << jb) - 1ULL;
                if (Bm & before) ind &= ~(1ULL << i); // earlier j beat i first
                ind &= ~(1ULL << jb);
            } else if (Bm) {
                ind &= ~(1ULL << i);
            }
        }
        out[lane]      = (float)((ind >> lane) & 1ULL);
        out[lane + 32] = (float)((ind >> (lane + 32)) & 1ULL);
    }
}

// ---------------------------------------------------------------------------
extern "C" void kernel_launch(void* const* d_in, const int* in_sizes, int n_in,
                              void* d_out, int out_size) {
    const float* mask = (const float*)d_in[0];
    // Best-effort: maximize smem carveout for occupancy (host attr, not a
    // stream op; safe under graph capture).
    static bool attr_done = false;
    if (!attr_done) {
        cudaFuncSetAttribute(pack_inter_kernel,
                             cudaFuncAttributePreferredSharedMemoryCarveout,
                             cudaSharedmemCarveoutMaxShared);
        attr_done = true;
    }
    pack_inter_kernel<<<NBLK, 256>>>(mask);
    nms_kernel<<<1, 256>>>((float*)d_out);
}

// round 4
// speedup vs baseline: 1.7241x; 1.2877x over previous
#include <cuda_runtime.h>
#include <cstdint>

// Fixed shapes: B=1, N=64, X=256, Y=256, Z=32
#define NINST 64
#define V (256*256*32)                 // 2,097,152 voxels / instance
#define CHUNK_VOX 512                  // voxels per chunk per instance
#define CHUNK_BYTES (CHUNK_VOX*4)      // 2048 B per bulk load
#define CHUNK_WORDS 16                 // packed words per chunk per instance
#define NCHUNK (V/CHUNK_VOX)           // 4096 chunks
#define GROUP 16                       // instances per TMA group / mbarrier
#define HALF_BYTES (GROUP*CHUNK_BYTES) // 32 KB per buffer half
#define NBLK 444                       // 148 SMs * 3 resident blocks
#define NSLOT 8                        // partial accumulator slots

// Dynamic smem layout
#define SM_RAW     0
#define SM_PACKED  (2*HALF_BYTES)                      // 65536
#define SM_MBAR    (SM_PACKED + CHUNK_WORDS*NINST*4)   // 69632
#define SM_CHUNK   (SM_MBAR + 16)                      // 69648
#define SM_TOTAL   69664

// Device state (zero-initialized at module load; the last block of every
// launch restores everything to zero, so graph replays start clean).
__device__ unsigned g_partial[NSLOT * NINST * NINST];
__device__ unsigned g_ticket;
__device__ unsigned g_done;

// ---------------------------------------------------------------------------
// PTX helpers
// ---------------------------------------------------------------------------
__device__ __forceinline__ unsigned su32(const void* p) {
    return (unsigned)__cvta_generic_to_shared(p);
}
__device__ __forceinline__ void mbar_init(unsigned a, unsigned cnt) {
    asm volatile("mbarrier.init.shared.b64 [%0], %1;" :: "r"(a), "r"(cnt) : "memory");
}
__device__ __forceinline__ void mbar_expect_tx(unsigned a, unsigned tx) {
    asm volatile("mbarrier.arrive.expect_tx.shared.b64 _, [%0], %1;"
                 :: "r"(a), "r"(tx) : "memory");
}
__device__ __forceinline__ void mbar_wait(unsigned a, unsigned parity) {
    asm volatile(
        "{\n\t.reg .pred p;\n\t"
        "WAIT_%=:\n\t"
        "mbarrier.try_wait.parity.acquire.cta.shared::cta.b64 p, [%0], %1, 0x989680;\n\t"
        "@!p bra WAIT_%=;\n\t}"
        :: "r"(a), "r"(parity) : "memory");
}
__device__ __forceinline__ void tma_bulk(unsigned dst, const void* src,
                                         unsigned bytes, unsigned mbar) {
    asm volatile(
        "cp.async.bulk.shared::cta.global.mbarrier::complete_tx::bytes [%0], [%1], %2, [%3];"
        :: "r"(dst), "l"(src), "r"(bytes), "r"(mbar) : "memory");
}
__device__ __forceinline__ void fence_async() {
    asm volatile("fence.proxy.async.shared::cta;" ::: "memory");
}

// ---------------------------------------------------------------------------
// Single fused kernel: persistent TMA-fed pack + pairwise popcount;
// last block reduces, runs exact-integer NMS, writes output, resets state.
// ---------------------------------------------------------------------------
extern __shared__ char smem[];

__global__ __launch_bounds__(256) void fused_nms_kernel(
    const float* __restrict__ mask, float* __restrict__ out)
{
    const unsigned sbase = su32(smem);
    unsigned (*packed)[NINST] = (unsigned (*)[NINST])(smem + SM_PACKED);
    int* s_chunk = (int*)(smem + SM_CHUNK);
    const unsigned mb[2] = {sbase + SM_MBAR, sbase + SM_MBAR + 8};

    const int tid  = threadIdx.x;
    const int lane = tid & 31;
    const int wp   = tid >> 5;

    if (tid == 0) {
        mbar_init(mb[0], 1);
        mbar_init(mb[1], 1);
        fence_async();
    }

    // 16x16 pair-tile map (4x4 instance pairs / thread), bank-conflict free.
    const int ti = ((wp & 1) << 3) + (lane & 7);
    const int tj = ((wp >> 1) << 2) + (lane >> 3);
    const int i0 = ti * 4, j0 = tj * 4;

    unsigned acc[4][4];
#pragma unroll
    for (int r = 0; r < 4; r++)
#pragma unroll
        for (int c2 = 0; c2 < 4; c2++) acc[r][c2] = 0u;

    // tid0: issue one group (16 instances x 2KB) into buffer half h.
    auto issue = [&](int g, int h, int c) {
        const float* src = mask + (size_t)c * CHUNK_VOX + (size_t)(g * GROUP) * V;
        const unsigned dst = sbase + SM_RAW + h * HALF_BYTES;
        mbar_expect_tx(mb[h], HALF_BYTES);
#pragma unroll
        for (int jj = 0; jj < GROUP; jj++)
            tma_bulk(dst + jj * CHUNK_BYTES, src + (size_t)jj * V,
                     CHUNK_BYTES, mb[h]);
    };

    // Prologue: first ticket + groups 0,1 in flight.
    if (tid == 0) {
        int t0 = (int)atomicAdd(&g_ticket, 1u);
        *s_chunk = t0;
        if (t0 < NCHUNK) { issue(0, 0, t0); issue(1, 1, t0); }
    }
    __syncthreads();
    int c = *s_chunk;

    const unsigned raw_rd = sbase + SM_RAW + (unsigned)(wp * 64 + lane * 2) * 4u;
    unsigned ph0 = 0, ph1 = 0;
    int nextc = NCHUNK;  // tid0-local

    while (c < NCHUNK) {
#pragma unroll
        for (int g = 0; g < 4; g++) {
            const int h = g & 1;
            if (h == 0) { mbar_wait(mb[0], ph0); ph0 ^= 1; }
            else        { mbar_wait(mb[1], ph1); ph1 ^= 1; }

            // Pack 16 instances: warp wp owns words wp*2, wp*2+1.
            const unsigned rbase = raw_rd + (unsigned)h * HALF_BYTES;
#pragma unroll
            for (int jj = 0; jj < GROUP; jj++) {
                uint2 v;
                asm volatile("ld.shared.v2.u32 {%0,%1}, [%2];"
                             : "=r"(v.x), "=r"(v.y)
                             : "r"(rbase + (unsigned)jj * CHUNK_BYTES));
                unsigned b0 = __ballot_sync(0xffffffffu, v.x != 0u);
                unsigned b1 = __ballot_sync(0xffffffffu, v.y != 0u);
                if (lane == 0) {
                    const int j = g * GROUP + jj;
                    packed[wp * 2][j]     = b0;
                    packed[wp * 2 + 1][j] = b1;
                }
            }
            __syncthreads();  // half h fully consumed; packed cols visible

            if (tid == 0) {
                fence_async();  // order generic reads before async refill
                if (g == 0)      issue(2, 0, c);
                else if (g == 1) issue(3, 1, c);
                else if (g == 2) {
                    nextc = (int)atomicAdd(&g_ticket, 1u);
                    *s_chunk = nextc;   // published by g3's __syncthreads
                    if (nextc < NCHUNK) issue(0, 0, nextc);
                } else {
                    if (nextc < NCHUNK) issue(1, 1, nextc);
                }
            }
        }

        // Phase B: accumulate this chunk's 64x64 intersections in registers.
        // (overlaps the next chunk's TMA loads already in flight)
#pragma unroll
        for (int w = 0; w < CHUNK_WORDS; w += 2) {
            uint4 A0 = *(const uint4*)&packed[w][i0];
            uint4 B0 = *(const uint4*)&packed[w][j0];
            uint4 A1 = *(const uint4*)&packed[w + 1][i0];
            uint4 B1 = *(const uint4*)&packed[w + 1][j0];
            unsigned a0[4] = {A0.x, A0.y, A0.z, A0.w};
            unsigned b0[4] = {B0.x, B0.y, B0.z, B0.w};
            unsigned a1[4] = {A1.x, A1.y, A1.z, A1.w};
            unsigned b1[4] = {B1.x, B1.y, B1.z, B1.w};
#pragma unroll
            for (int r = 0; r < 4; r++)
#pragma unroll
                for (int c2 = 0; c2 < 4; c2++)
                    acc[r][c2] += __popc(a0[r] & b0[c2]) + __popc(a1[r] & b1[c2]);
        }
        __syncthreads();  // protect packed[] against next chunk's pack writes
        c = *s_chunk;
    }

    // Flush per-block totals (16 atomics / thread, NSLOT-way spread).
    {
        unsigned* gp =
            g_partial + (unsigned)(blockIdx.x & (NSLOT - 1)) * (NINST * NINST);
#pragma unroll
        for (int r = 0; r < 4; r++)
#pragma unroll
            for (int c2 = 0; c2 < 4; c2++)
                atomicAdd(&gp[(i0 + r) * NINST + (j0 + c2)], acc[r][c2]);
    }
    __threadfence();
    __syncthreads();
    if (tid == 0) *s_chunk = (int)atomicAdd(&g_done, 1u);
    __syncthreads();
    if (*s_chunk != NBLK - 1) return;

    // ------------------- Last block: reduce + NMS + reset -------------------
    unsigned* inter = (unsigned*)smem;             // 16 KB (raw area is dead)
    unsigned* ssc   = (unsigned*)(smem + 16384);

    {   // vectorized reduce of NSLOT slots (L1-bypassing loads)
        const uint4* gp4 = (const uint4*)g_partial;   // [NSLOT][1024] uint4
        uint4* in4 = (uint4*)inter;
        for (int e = tid; e < (NINST * NINST) / 4; e += 256) {
            uint4 s = make_uint4(0u, 0u, 0u, 0u);
#pragma unroll
            for (int k = 0; k < NSLOT; k++) {
                uint4 v = __ldcg(&gp4[k * (NINST * NINST / 4) + e]);
                s.x += v.x; s.y += v.y; s.z += v.z; s.w += v.w;
            }
            in4[e] = s;
        }
    }
    __syncthreads();

    {   // reset device state for the next replay
        uint4 z = make_uint4(0u, 0u, 0u, 0u);
        uint4* gz = (uint4*)g_partial;
        for (int e = tid; e < (NSLOT * NINST * NINST) / 4; e += 256) gz[e] = z;
        if (tid == 0) { g_ticket = 0u; g_done = 0u; }
    }

    if (tid < NINST) ssc[tid] = inter[tid * NINST + tid];  // score = diagonal
    __syncthreads();

    if (tid < 32) {
        const unsigned sj0 = ssc[lane];
        const unsigned sj1 = ssc[lane + 32];
        unsigned long long ind = ~0ULL;

        for (int i = 0; i < NINST; i++) {
            if (!((ind >> i) & 1ULL)) continue;  // warp-uniform
            const unsigned si  = ssc[i];
            const unsigned in0 = inter[i * NINST + lane];
            const unsigned in1 = inter[i * NINST + lane + 32];
            // iou > 0.5 <=> 2*inter > union (exact integers; counts < 2^23)
            const bool h0 = (2u * in0 > si + sj0 - in0);
            const bool h1 = (2u * in1 > si + sj1 - in1);
            unsigned a0 = __ballot_sync(0xffffffffu, h0 && (si > sj0));
            unsigned a1 = __ballot_sync(0xffffffffu, h1 && (si > sj1));
            unsigned c0 = __ballot_sync(0xffffffffu, h0 && (sj0 > si));
            unsigned c1 = __ballot_sync(0xffffffffu, h1 && (sj1 > si));
            unsigned long long A  = ((unsigned long long)a1 << 32) | a0;
            unsigned long long Bm = ((unsigned long long)c1 << 32) | c0;
            if (A) {
                int jb = __ffsll((long long)A) - 1;   // first break j
                unsigned long long before = (1ULL << jb) - 1ULL;
                if (Bm & before) ind &= ~(1ULL << i); // earlier j beat i first
                ind &= ~(1ULL << jb);
            } else if (Bm) {
                ind &= ~(1ULL << i);
            }
        }
        out[lane]      = (float)((ind >> lane) & 1ULL);
        out[lane + 32] = (float)((ind >> (lane + 32)) & 1ULL);
    }
}

// ---------------------------------------------------------------------------
extern "C" void kernel_launch(void* const* d_in, const int* in_sizes, int n_in,
                              void* d_out, int out_size) {
    const float* mask = (const float*)d_in[0];
    static bool attr_done = false;
    if (!attr_done) {  // host-side attrs: first (pre-capture) call sets them
        cudaFuncSetAttribute(fused_nms_kernel,
                             cudaFuncAttributeMaxDynamicSharedMemorySize,
                             SM_TOTAL);
        cudaFuncSetAttribute(fused_nms_kernel,
                             cudaFuncAttributePreferredSharedMemoryCarveout,
                             cudaSharedmemCarveoutMaxShared);
        attr_done = true;
    }
    fused_nms_kernel<<<NBLK, 256, SM_TOTAL>>>(mask, (float*)d_out);
}